// round 15
// baseline (speedup 1.0000x reference)
#include <cuda_runtime.h>
#include <cuda_bf16.h>
#include <math.h>
#include <stdint.h>

#define BB 64
#define LL 1024
#define DD 256
#define TWO_D 512
#define HD 1280

typedef __nv_bfloat16 bf16;
typedef __nv_bfloat162 bf162;

// ---------------- scratch (device globals) ----------------
__device__ bf16 g_LIS[(size_t)BB * LL * TWO_D];      // [B*L][512] (qe|ce)
__device__ bf16 g_S[(size_t)BB * LL * LL];           // [B][L][L] exp'd causal P
__device__ bf16 g_HRPq[(size_t)BB * LL * DD];        // [B*L][256] qe-half of HRP only
__device__ bf16 g_x[(size_t)BB * LL * DD];           // ping
__device__ bf16 g_x2[(size_t)BB * LL * DD];          // pong
__device__ bf16 g_cqc[(size_t)BB * LL * DD];
__device__ bf16 g_WmlpP[(size_t)TWO_D * HD];         // packed [pn=512][k=1280]
__device__ float g_bP[TWO_D];                        // packed mlp bias
__device__ bf16 g_convwP[(size_t)3 * TWO_D * 1024];  // packed [l][pn=512][k=1024]
__device__ float g_bconvP[3 * TWO_D];                // packed conv bias
__device__ float g_rowsum[(size_t)BB * LL];          // sum_{j<i} e_ij
__device__ float g_s1[(size_t)BB * LL];              // sum_{j<i, c_j=1} e_ij
__device__ float g_pii[(size_t)BB * LL];             // e_ii
__device__ float g_u1[2 * TWO_D];                    // Ec[e] . W[:,256:512]  (packed n)
__device__ float g_u2[2 * TWO_D];                    // Ec[e] . W[:,768:1024] (packed n)

__device__ __forceinline__ float sigmoidf_(float v) { return 1.f / (1.f + __expf(-v)); }

__device__ __forceinline__ float expp(float x) {
    float e = fmaf(x, 0.00833333f, 0.04166667f);
    e = fmaf(x, e, 0.16666667f);
    e = fmaf(x, e, 0.5f);
    e = fmaf(x, e, 1.0f);
    e = fmaf(x, e, 1.0f);
    if (fabsf(x) > 0.5f) e = __expf(x);
    return e;
}

// packed col mapping: pn = 64*s + c; c<32 -> a-col s*32+c ; else gate-col 256+s*32+(c-32)
__device__ __forceinline__ int unpackN64(int pn) {
    int s = pn >> 6, c = pn & 63;
    return (c < 32) ? s * 32 + c : 256 + s * 32 + (c - 32);
}

// ---------------- async copy ----------------
__device__ __forceinline__ uint32_t s2u(const void* p) {
    return (uint32_t)__cvta_generic_to_shared(p);
}
__device__ __forceinline__ void cp16(char* dst, const void* src, bool v) {
    asm volatile("cp.async.cg.shared.global [%0], [%1], 16, %2;"
                 :: "r"(s2u(dst)), "l"(src), "r"(v ? 16 : 0));
}
#define CP_COMMIT() asm volatile("cp.async.commit_group;" ::: "memory")

// ---------------- mma ----------------
__device__ __forceinline__ void mma_bf16(float* c, const uint32_t* a, const uint32_t* b) {
    asm volatile(
        "mma.sync.aligned.m16n8k16.row.col.f32.bf16.bf16.f32 "
        "{%0,%1,%2,%3}, {%4,%5,%6,%7}, {%8,%9}, {%0,%1,%2,%3};"
        : "+f"(c[0]), "+f"(c[1]), "+f"(c[2]), "+f"(c[3])
        : "r"(a[0]), "r"(a[1]), "r"(a[2]), "r"(a[3]), "r"(b[0]), "r"(b[1]));
}

// ---------------- swizzles ----------------
__device__ __forceinline__ uint32_t swz128(uint32_t off) {
    return off ^ ((off >> 3) & 0x70);
}
__device__ __forceinline__ uint32_t swzkn(uint32_t row, uint32_t cb) {
    uint32_t unit = (cb >> 4) & 7;
    return row * 256 + (cb & 0x80) + ((unit ^ (row & 7)) << 4) + (cb & 15);
}

// ---------------- one K=64 chunk (128x128 CTA tile, 8 warps 4x2, 32x64 warp) ----
// ks-order staggered by wm so warps' LDSM and MMA phases interleave on the SM.
template <bool BT>
__device__ __forceinline__ void warp_k64(const char* As, const char* Bs,
                                         float acc[16][4], int wm, int wn, int lane) {
    uint32_t abase = s2u(As), bbase = s2u(Bs);
#pragma unroll
    for (int kk = 0; kk < 4; kk++) {
        int ks16 = (kk + wm) & 3;
        int ks = ks16 * 16;
        uint32_t a[2][4];
#pragma unroll
        for (int t = 0; t < 2; t++) {
            uint32_t row = wm * 32 + t * 16 + ((lane >> 3) & 1) * 8 + (lane & 7);
            uint32_t cb = (ks + (lane >> 4) * 8) * 2;
            uint32_t ad = abase + swz128(row * 128 + cb);
            asm volatile("ldmatrix.sync.aligned.m8n8.x4.shared.b16 {%0,%1,%2,%3},[%4];"
                         : "=r"(a[t][0]), "=r"(a[t][1]), "=r"(a[t][2]), "=r"(a[t][3])
                         : "r"(ad));
        }
        uint32_t b[8][2];
#pragma unroll
        for (int p4 = 0; p4 < 4; p4++) {
            uint32_t r0, r1, r2, r3;
            if (BT) {
                uint32_t row = ks + ((lane >> 3) & 1) * 8 + (lane & 7);
                uint32_t cb = (wn * 64 + p4 * 16 + (lane >> 4) * 8) * 2;
                uint32_t ad = bbase + swzkn(row, cb);
                asm volatile("ldmatrix.sync.aligned.m8n8.x4.trans.shared.b16 {%0,%1,%2,%3},[%4];"
                             : "=r"(r0), "=r"(r1), "=r"(r2), "=r"(r3) : "r"(ad));
            } else {
                uint32_t row = wn * 64 + p4 * 16 + (lane >> 4) * 8 + (lane & 7);
                uint32_t cb = (ks + ((lane >> 3) & 1) * 8) * 2;
                uint32_t ad = bbase + swz128(row * 128 + cb);
                asm volatile("ldmatrix.sync.aligned.m8n8.x4.shared.b16 {%0,%1,%2,%3},[%4];"
                             : "=r"(r0), "=r"(r1), "=r"(r2), "=r"(r3) : "r"(ad));
            }
            b[2 * p4][0] = r0; b[2 * p4][1] = r1;
            b[2 * p4 + 1][0] = r2; b[2 * p4 + 1][1] = r3;
        }
#pragma unroll
        for (int t = 0; t < 2; t++)
#pragma unroll
            for (int j = 0; j < 8; j++)
                mma_bf16(acc[t * 8 + j], a[t], b[j]);
    }
}

// ---------------- pipelined GEMM kernel ----------------
// MODE 0=scores(+exp+rowsum+s1) 1=hrp-qe(+renorm) 2=mlp(+GLU+rank2 ce) 3=conv(+GLU+res)
#define STAGE_BYTES 16384
#define B_SMEM_OFF  (3 * 16384)
#define SMEM_TOTAL  (6 * 16384)

template <int MODE>
__device__ __forceinline__ void load_chunk(char* smem, int s, int k0, int tid,
                                           int bx, int by, int bz, int layer,
                                           const bf16* xsrc) {
    char* Ab = smem + s * STAGE_BYTES;
    char* Bb = smem + B_SMEM_OFF + s * STAGE_BYTES;
    {
        int row = tid >> 1, h = tid & 1;
        const bf16* src; bool v = true;
        if (MODE == 0) {
            src = g_LIS + ((size_t)(bz * LL + by * 128 + row) * TWO_D + k0);
        } else if (MODE == 1) {
            src = g_S + ((size_t)(bz * LL + by * 128 + row) * LL + k0);
        } else if (MODE == 2) {
            int r = by * 128 + row;
            if (k0 < 256)      src = g_LIS + ((size_t)r * TWO_D + k0);
            else if (k0 < 512) src = g_HRPq + ((size_t)r * DD + (k0 - 256));
            else               src = g_cqc + ((size_t)r * DD + (k0 - 512));
        } else {
            int ls = by * 128 + row + (k0 >> 8) - 3;
            v = (ls >= 0); if (!v) ls = 0;
            src = xsrc + ((size_t)(bz * LL + ls) * DD + (k0 & 255));
        }
#pragma unroll
        for (int j = 0; j < 4; j++) {
            uint32_t cb = h * 64 + j * 16;
            cp16(Ab + swz128((uint32_t)row * 128 + cb), src + cb / 2, v);
        }
    }
    if (MODE == 1) {
        int row = tid >> 2, q = tid & 3;
        const bf16* src = g_LIS + ((size_t)(bz * LL + k0 + row) * TWO_D + bx * 128); // qe cols
#pragma unroll
        for (int j = 0; j < 4; j++) {
            uint32_t cb = q * 64 + j * 16;
            cp16(Bb + swzkn((uint32_t)row, cb), src + cb / 2, true);
        }
    } else {
        int row = tid >> 1, h = tid & 1;
        const bf16* src;
        if (MODE == 0)      src = g_LIS + ((size_t)(bz * LL + bx * 128 + row) * TWO_D + k0);
        else if (MODE == 2) {
            // reduced K -> original weight column: qe->0:256, HRPq->512:768, cqc->1024:1280
            int kw = (k0 < 256) ? k0 : ((k0 < 512) ? k0 + 256 : k0 + 512);
            src = g_WmlpP + ((size_t)(bx * 128 + row) * HD + kw);
        }
        else                src = g_convwP + ((size_t)(layer * TWO_D + bx * 128 + row)) * 1024 + k0;
#pragma unroll
        for (int j = 0; j < 4; j++) {
            uint32_t cb = h * 64 + j * 16;
            cp16(Bb + swz128((uint32_t)row * 128 + cb), src + cb / 2, true);
        }
    }
}

template <int MODE>
__global__ void __launch_bounds__(256, 2) k_gemm(const bf16* __restrict__ xsrc,
                                                 bf16* __restrict__ xdst,
                                                 const float* __restrict__ biasP,
                                                 int layer,
                                                 const int* __restrict__ csrc) {
    extern __shared__ char smem[];
    int tid = threadIdx.x, wid = tid >> 5, lane = tid & 31;
    int bx = blockIdx.x, by = blockIdx.y, bz = blockIdx.z;
    if (MODE == 0 && bx > by) return;
    int nch = (MODE == 0) ? 4 : (MODE == 1) ? (by + 1) * 2 : (MODE == 2) ? 12 : 16;
    int wm = wid >> 1, wn = wid & 1;

    float acc[16][4] = {};

    load_chunk<MODE>(smem, 0, 0, tid, bx, by, bz, layer, xsrc);  CP_COMMIT();
    load_chunk<MODE>(smem, 1, 64, tid, bx, by, bz, layer, xsrc); CP_COMMIT();

#pragma unroll 1
    for (int i = 0; i < nch; i++) {
        int s = i % 3;
        if (i == nch - 1) asm volatile("cp.async.wait_group 0;" ::: "memory");
        else              asm volatile("cp.async.wait_group 1;" ::: "memory");
        __syncthreads();
        if (i + 2 < nch) {
            load_chunk<MODE>(smem, (i + 2) % 3, (i + 2) * 64, tid, bx, by, bz, layer, xsrc);
            CP_COMMIT();
        }
        warp_k64<(MODE == 1)>(smem + s * STAGE_BYTES, smem + B_SMEM_OFF + s * STAGE_BYTES,
                              acc, wm, wn, lane);
    }

    if (MODE == 0) {
        __syncthreads();
        int* cv = (int*)smem;
        if (tid < 128) cv[tid] = csrc[bz * LL + bx * 128 + tid];
        __syncthreads();
        bf16* out = g_S + ((size_t)(bz * LL + by * 128)) * LL + bx * 128;
        float* rs = g_rowsum + (size_t)bz * LL;
        float* s1g = g_s1 + (size_t)bz * LL;
        float* pii = g_pii + (size_t)bz * LL;
#pragma unroll
        for (int t = 0; t < 2; t++) {
            int r = wm * 32 + t * 16 + (lane >> 2);
            int gi0 = by * 128 + r, gi1 = gi0 + 8;
            float s0 = 0.f, s1 = 0.f;
            float m0 = 0.f, m1 = 0.f;
#pragma unroll
            for (int j = 0; j < 8; j++) {
                int cc = wn * 64 + j * 8 + (lane & 3) * 2;
                int gc = bx * 128 + cc;
                int cm0 = cv[cc], cm1 = cv[cc + 1];
                float* a = acc[t * 8 + j];
                float e0 = expp(a[0]), e1 = expp(a[1]);
                float e2 = expp(a[2]), e3 = expp(a[3]);
                if (gc == gi0)     pii[gi0] = e0;
                if (gc + 1 == gi0) pii[gi0] = e1;
                if (gc == gi1)     pii[gi1] = e2;
                if (gc + 1 == gi1) pii[gi1] = e3;
                float p0 = (gc < gi0)     ? e0 : 0.f;
                float p1 = (gc + 1 < gi0) ? e1 : 0.f;
                float p2 = (gc < gi1)     ? e2 : 0.f;
                float p3 = (gc + 1 < gi1) ? e3 : 0.f;
                s0 += p0 + p1; s1 += p2 + p3;
                m0 += (cm0 ? p0 : 0.f) + (cm1 ? p1 : 0.f);
                m1 += (cm0 ? p2 : 0.f) + (cm1 ? p3 : 0.f);
                *(bf162*)(out + (size_t)r * LL + cc)       = __floats2bfloat162_rn(p0, p1);
                *(bf162*)(out + (size_t)(r + 8) * LL + cc) = __floats2bfloat162_rn(p2, p3);
            }
#pragma unroll
            for (int off = 1; off <= 2; off <<= 1) {
                s0 += __shfl_xor_sync(0xffffffffu, s0, off);
                s1 += __shfl_xor_sync(0xffffffffu, s1, off);
                m0 += __shfl_xor_sync(0xffffffffu, m0, off);
                m1 += __shfl_xor_sync(0xffffffffu, m1, off);
            }
            if ((lane & 3) == 0) {
                atomicAdd(&rs[gi0], s0);
                atomicAdd(&rs[gi1], s1);
                atomicAdd(&s1g[gi0], m0);
                atomicAdd(&s1g[gi1], m1);
            }
        }
    } else if (MODE == 1) {
        bf16* out = g_HRPq + ((size_t)(bz * LL + by * 128)) * DD + bx * 128;
        const float* rs = g_rowsum + (size_t)bz * LL;
        const float* pii = g_pii + (size_t)bz * LL;
#pragma unroll
        for (int t = 0; t < 2; t++) {
            int r = wm * 32 + t * 16 + (lane >> 2);
            int gi0 = by * 128 + r, gi1 = gi0 + 8;
            float r0 = rs[gi0], r1 = rs[gi1];
            float inv0 = 1.f / (r0 + 1e-8f * (r0 + pii[gi0]));
            float inv1 = 1.f / (r1 + 1e-8f * (r1 + pii[gi1]));
#pragma unroll
            for (int j = 0; j < 8; j++) {
                int cc = wn * 64 + j * 8 + (lane & 3) * 2;
                float* a = acc[t * 8 + j];
                *(bf162*)(out + (size_t)r * DD + cc) =
                    __floats2bfloat162_rn(a[0] * inv0, a[1] * inv0);
                *(bf162*)(out + (size_t)(r + 8) * DD + cc) =
                    __floats2bfloat162_rn(a[2] * inv1, a[3] * inv1);
            }
        }
    } else {
        // GLU epilogue; MODE 2 folds exact ce-contributions (alpha/beta inline)
#pragma unroll
        for (int t = 0; t < 2; t++) {
            int r = wm * 32 + t * 16 + (lane >> 2);
            size_t gr0 = (MODE == 2) ? (size_t)(by * 128 + r)
                                     : ((size_t)bz * LL + by * 128 + r);
            size_t gr1 = gr0 + 8;
            float al0 = 0.f, be0 = 0.f, al1 = 0.f, be1 = 0.f;
            int cr0 = 0, cr1 = 0;
            if (MODE == 2) {
                float rsa = g_rowsum[gr0], s1a = g_s1[gr0], pia = g_pii[gr0];
                float inva = 1.f / (rsa + 1e-8f * (rsa + pia));
                al0 = (rsa - s1a) * inva; be0 = s1a * inva; cr0 = csrc[gr0];
                float rsb = g_rowsum[gr1], s1b = g_s1[gr1], pib = g_pii[gr1];
                float invb = 1.f / (rsb + 1e-8f * (rsb + pib));
                al1 = (rsb - s1b) * invb; be1 = s1b * invb; cr1 = csrc[gr1];
            }
#pragma unroll
            for (int j = 0; j < 4; j++) {
                int pc = wn * 64 + j * 8 + (lane & 3) * 2;
                int pnA = bx * 128 + pc, pnG = pnA + 32;
                float ba0 = biasP[pnA], ba1 = biasP[pnA + 1];
                float bg0 = biasP[pnG], bg1 = biasP[pnG + 1];
                float aA0r0 = 0, aA1r0 = 0, aG0r0 = 0, aG1r0 = 0;
                float aA0r1 = 0, aA1r1 = 0, aG0r1 = 0, aG1r1 = 0;
                if (MODE == 2) {
                    float u1A0c0 = g_u1[cr0 * TWO_D + pnA], u1A1c0 = g_u1[cr0 * TWO_D + pnA + 1];
                    float u1G0c0 = g_u1[cr0 * TWO_D + pnG], u1G1c0 = g_u1[cr0 * TWO_D + pnG + 1];
                    float u1A0c1 = g_u1[cr1 * TWO_D + pnA], u1A1c1 = g_u1[cr1 * TWO_D + pnA + 1];
                    float u1G0c1 = g_u1[cr1 * TWO_D + pnG], u1G1c1 = g_u1[cr1 * TWO_D + pnG + 1];
                    float u2A00 = g_u2[pnA], u2A10 = g_u2[pnA + 1];
                    float u2G00 = g_u2[pnG], u2G10 = g_u2[pnG + 1];
                    float u2A01 = g_u2[TWO_D + pnA], u2A11 = g_u2[TWO_D + pnA + 1];
                    float u2G01 = g_u2[TWO_D + pnG], u2G11 = g_u2[TWO_D + pnG + 1];
                    aA0r0 = u1A0c0 + al0 * u2A00 + be0 * u2A01;
                    aA1r0 = u1A1c0 + al0 * u2A10 + be0 * u2A11;
                    aG0r0 = u1G0c0 + al0 * u2G00 + be0 * u2G01;
                    aG1r0 = u1G1c0 + al0 * u2G10 + be0 * u2G11;
                    aA0r1 = u1A0c1 + al1 * u2A00 + be1 * u2A01;
                    aA1r1 = u1A1c1 + al1 * u2A10 + be1 * u2A11;
                    aG0r1 = u1G0c1 + al1 * u2G00 + be1 * u2G01;
                    aG1r1 = u1G1c1 + al1 * u2G10 + be1 * u2G11;
                }
                float* a = acc[t * 8 + j];
                float* g = acc[t * 8 + j + 4];
                int ocol = (bx * 2 + wn) * 32 + j * 8 + (lane & 3) * 2;
                float v0 = (a[0] + ba0 + aA0r0) * sigmoidf_(g[0] + bg0 + aG0r0);
                float v1 = (a[1] + ba1 + aA1r0) * sigmoidf_(g[1] + bg1 + aG1r0);
                float v2 = (a[2] + ba0 + aA0r1) * sigmoidf_(g[2] + bg0 + aG0r1);
                float v3 = (a[3] + ba1 + aA1r1) * sigmoidf_(g[3] + bg1 + aG1r1);
                if (MODE == 3) {
                    bf162 r0 = *(const bf162*)(xsrc + gr0 * DD + ocol);
                    bf162 r1 = *(const bf162*)(xsrc + gr1 * DD + ocol);
                    v0 += __bfloat162float(r0.x); v1 += __bfloat162float(r0.y);
                    v2 += __bfloat162float(r1.x); v3 += __bfloat162float(r1.y);
                }
                *(bf162*)(xdst + gr0 * DD + ocol) = __floats2bfloat162_rn(v0, v1);
                *(bf162*)(xdst + gr1 * DD + ocol) = __floats2bfloat162_rn(v2, v3);
            }
        }
    }
}

// ---------------- prep A: zero sums + embed (critical path for scores) ----------------
#define PA0 256
#define PA1 (PA0 + 65536)
__global__ __launch_bounds__(256) void k_prep_embed(const int* __restrict__ q,
                                                    const int* __restrict__ c,
                                                    const float* __restrict__ Eq,
                                                    const float* __restrict__ Ec) {
    int bid = blockIdx.x, tid = threadIdx.x;
    if (bid < PA0) {
        int id = bid * 256 + tid;
        g_rowsum[id] = 0.f;
        g_s1[id] = 0.f;
    } else {
        int r = bid - PA0, d = tid;
        int qi = q[r], ci = c[r];
        g_LIS[(size_t)r * TWO_D + d]      = __float2bfloat16(Eq[(size_t)qi * DD + d]);
        g_LIS[(size_t)r * TWO_D + DD + d] = __float2bfloat16(Ec[(size_t)ci * DD + d]);
    }
}

// ---------------- prep B: weights/u/cqc (overlapped on side stream) ----------------
#define PB0 2560
#define PB2 (PB0 + 2)
#define PBU (PB2 + 8)
#define PB3 (PBU + 768)
#define PB4 (PB3 + 16384)
__global__ __launch_bounds__(256) void k_prep_rest(const float* __restrict__ W1w,
                                                   const float* __restrict__ W2w,
                                                   const float* __restrict__ b1,
                                                   const float* __restrict__ b2,
                                                   const float* __restrict__ convb,
                                                   const float* __restrict__ convw,
                                                   const float* __restrict__ cqc,
                                                   const float* __restrict__ Ec) {
    __shared__ bf16 tile[64][40];
    int bid = blockIdx.x, tid = threadIdx.x;
    if (bid < PB0) {
        int id = bid * 256 + tid;
        if (id < TWO_D * HD) {
            int pn = id / HD, k = id % HD;
            int n = unpackN64(pn);
            float v = (n < DD) ? W1w[(size_t)n * HD + k] : W2w[(size_t)(n - DD) * HD + k];
            g_WmlpP[id] = __float2bfloat16(v);
        }
    } else if (bid < PB2) {
        int pn = (bid - PB0) * 256 + tid;
        int n = unpackN64(pn);
        g_bP[pn] = (n < DD) ? b1[n] : b2[n - DD];
        for (int l = 0; l < 3; l++)
            g_bconvP[l * TWO_D + pn] = convb[l * TWO_D + n];
    } else if (bid < PBU) {
        int t = (bid - PB2) * 256 + tid;
        int table = t >> 10;
        int rem = t & 1023;
        int e = rem >> 9, pn = rem & 511;
        int n = unpackN64(pn);
        const float* wr = (n < DD) ? (W1w + (size_t)n * HD) : (W2w + (size_t)(n - DD) * HD);
        int ko = table ? 768 : 256;
        const float* ec = Ec + e * DD;
        float s = 0.f;
        for (int k = 0; k < DD; k++) s += ec[k] * wr[ko + k];
        if (table == 0) g_u1[e * TWO_D + pn] = s;
        else            g_u2[e * TWO_D + pn] = s;
    } else if (bid < PB3) {
        int id = bid - PBU;
        int kx = id & 15, ny = (id >> 4) & 15, l = id >> 8;
        int k0 = kx * 64, n0 = ny * 32;
        {
            int row = tid >> 2, seg = tid & 3;
            const float* src = convw + ((size_t)(l * 1024 + k0 + row)) * TWO_D + n0 + seg * 8;
            float4 v0 = *(const float4*)src;
            float4 v1 = *(const float4*)(src + 4);
            tile[row][seg * 8 + 0] = __float2bfloat16(v0.x);
            tile[row][seg * 8 + 1] = __float2bfloat16(v0.y);
            tile[row][seg * 8 + 2] = __float2bfloat16(v0.z);
            tile[row][seg * 8 + 3] = __float2bfloat16(v0.w);
            tile[row][seg * 8 + 4] = __float2bfloat16(v1.x);
            tile[row][seg * 8 + 5] = __float2bfloat16(v1.y);
            tile[row][seg * 8 + 6] = __float2bfloat16(v1.z);
            tile[row][seg * 8 + 7] = __float2bfloat16(v1.w);
        }
        __syncthreads();
        {
            int s = (n0 < 256) ? (n0 >> 5) : ((n0 - 256) >> 5);
            int pn0 = s * 64 + ((n0 < 256) ? 0 : 32);
            int row = tid >> 3, seg = tid & 7;
            bf16 buf[8];
#pragma unroll
            for (int j = 0; j < 8; j++) buf[j] = tile[seg * 8 + j][row];
            bf16* dst = g_convwP + ((size_t)(l * TWO_D + pn0 + row)) * 1024 + k0 + seg * 8;
            *(uint4*)dst = *(uint4*)buf;
        }
    } else {
        size_t id = (size_t)(bid - PB3) * 256 + tid;
        float4 v = ((const float4*)cqc)[id];
        bf162* o = (bf162*)g_cqc;
        o[id * 2] = __floats2bfloat162_rn(v.x, v.y);
        o[id * 2 + 1] = __floats2bfloat162_rn(v.z, v.w);
    }
}

// ---------------- predict ----------------
__global__ __launch_bounds__(256) void k_predict(const bf16* __restrict__ xf,
                                                 float* __restrict__ out) {
    int warp = threadIdx.x >> 5, lane = threadIdx.x & 31;
    int o = blockIdx.x * 8 + warp;
    if (o >= BB * (LL - 1)) return;
    int b = o / (LL - 1), l = o % (LL - 1);
    const bf16* xr = xf + (size_t)(b * LL + l) * DD;
    const bf16* qr = g_LIS + (size_t)(b * LL + l + 1) * TWO_D;
    float s = 0.f;
    for (int d = lane; d < DD; d += 32)
        s += __bfloat162float(xr[d]) * __bfloat162float(qr[d]);
#pragma unroll
    for (int off = 16; off > 0; off >>= 1) s += __shfl_down_sync(0xffffffffu, s, off);
    if (lane == 0) out[o] = sigmoidf_(s);
}

static bf16* addr_x() { void* p; cudaGetSymbolAddress(&p, g_x); return (bf16*)p; }
static bf16* addr_x2() { void* p; cudaGetSymbolAddress(&p, g_x2); return (bf16*)p; }
static float* addr_bP() { void* p; cudaGetSymbolAddress(&p, g_bP); return (float*)p; }
static float* addr_bconvP() { void* p; cudaGetSymbolAddress(&p, g_bconvP); return (float*)p; }

// ---------------- launch ----------------
extern "C" void kernel_launch(void* const* d_in, const int* in_sizes, int n_in,
                              void* d_out, int out_size) {
    (void)in_sizes; (void)n_in; (void)out_size;
    const int*   q     = (const int*)d_in[0];
    const int*   c     = (const int*)d_in[1];
    const float* cqc   = (const float*)d_in[2];
    const float* Eq    = (const float*)d_in[3];
    const float* Ec    = (const float*)d_in[4];
    const float* W1w   = (const float*)d_in[5];
    const float* W1b   = (const float*)d_in[6];
    const float* W2w   = (const float*)d_in[7];
    const float* W2b   = (const float*)d_in[8];
    const float* convw = (const float*)d_in[9];
    const float* convb = (const float*)d_in[10];
    float* out = (float*)d_out;

    static bf16 *xA = nullptr, *xB = nullptr;
    static float *bP = nullptr, *bconvP = nullptr;
    static cudaStream_t s2;
    static cudaEvent_t evF, evJ;
    static bool init_done = false;
    if (!init_done) {
        cudaFuncSetAttribute(k_gemm<0>, cudaFuncAttributeMaxDynamicSharedMemorySize, SMEM_TOTAL);
        cudaFuncSetAttribute(k_gemm<1>, cudaFuncAttributeMaxDynamicSharedMemorySize, SMEM_TOTAL);
        cudaFuncSetAttribute(k_gemm<2>, cudaFuncAttributeMaxDynamicSharedMemorySize, SMEM_TOTAL);
        cudaFuncSetAttribute(k_gemm<3>, cudaFuncAttributeMaxDynamicSharedMemorySize, SMEM_TOTAL);
        xA = addr_x(); xB = addr_x2();
        bP = addr_bP(); bconvP = addr_bconvP();
        cudaStreamCreateWithFlags(&s2, cudaStreamNonBlocking);
        cudaEventCreateWithFlags(&evF, cudaEventDisableTiming);
        cudaEventCreateWithFlags(&evJ, cudaEventDisableTiming);
        init_done = true;
    }

    // fork: prep_rest runs on side stream, overlapped with embed/scores/hrp
    cudaEventRecord(evF, 0);
    cudaStreamWaitEvent(s2, evF, 0);
    k_prep_rest<<<PB4, 256, 0, s2>>>(W1w, W2w, W1b, W2b, convb, convw, cqc, Ec);
    cudaEventRecord(evJ, s2);

    k_prep_embed<<<PA1, 256>>>(q, c, Eq, Ec);
    k_gemm<0><<<dim3(8, 8, BB), 256, SMEM_TOTAL>>>(nullptr, nullptr, nullptr, 0, c);
    k_gemm<1><<<dim3(2, 8, BB), 256, SMEM_TOTAL>>>(nullptr, nullptr, nullptr, 0, nullptr);

    // join before MLP (needs WmlpP/u/cqc/bias)
    cudaStreamWaitEvent(0, evJ, 0);
    k_gemm<2><<<dim3(4, 512, 1), 256, SMEM_TOTAL>>>(nullptr, xA, bP, 0, c);
    bf16* src = xA;
    bf16* dst = xB;
    for (int l = 0; l < 3; l++) {
        k_gemm<3><<<dim3(4, 8, BB), 256, SMEM_TOTAL>>>(src, dst, bconvP + l * TWO_D, l, nullptr);
        bf16* t = src; src = dst; dst = t;
    }
    k_predict<<<(BB * (LL - 1) + 7) / 8, 256>>>(src, out);
}

// round 16
// speedup vs baseline: 1.1477x; 1.1477x over previous
#include <cuda_runtime.h>
#include <cuda_bf16.h>
#include <math.h>
#include <stdint.h>

#define BB 64
#define LL 1024
#define DD 256
#define TWO_D 512
#define HD 1280

typedef __nv_bfloat16 bf16;
typedef __nv_bfloat162 bf162;

// ---------------- scratch (device globals) ----------------
__device__ bf16 g_LIS[(size_t)BB * LL * TWO_D];
__device__ bf16 g_S[(size_t)BB * LL * LL];
__device__ bf16 g_HRPq[(size_t)BB * LL * DD];
__device__ bf16 g_x[(size_t)BB * LL * DD];
__device__ bf16 g_x2[(size_t)BB * LL * DD];
__device__ bf16 g_cqc[(size_t)BB * LL * DD];
__device__ bf16 g_WmlpP[(size_t)TWO_D * HD];
__device__ float g_bP[TWO_D];
__device__ bf16 g_convwP[(size_t)3 * TWO_D * 1024];
__device__ float g_bconvP[3 * TWO_D];
__device__ float g_rowsum[(size_t)BB * LL];
__device__ float g_s1[(size_t)BB * LL];
__device__ float g_pii[(size_t)BB * LL];
__device__ float g_u1[2 * TWO_D];
__device__ float g_u2[2 * TWO_D];

__device__ __forceinline__ float sigmoidf_(float v) { return 1.f / (1.f + __expf(-v)); }

__device__ __forceinline__ float expp(float x) {
    float e = fmaf(x, 0.00833333f, 0.04166667f);
    e = fmaf(x, e, 0.16666667f);
    e = fmaf(x, e, 0.5f);
    e = fmaf(x, e, 1.0f);
    e = fmaf(x, e, 1.0f);
    if (fabsf(x) > 0.5f) e = __expf(x);
    return e;
}

__device__ __forceinline__ int unpackN64(int pn) {
    int s = pn >> 6, c = pn & 63;
    return (c < 32) ? s * 32 + c : 256 + s * 32 + (c - 32);
}

// ---------------- async copy ----------------
__device__ __forceinline__ uint32_t s2u(const void* p) {
    return (uint32_t)__cvta_generic_to_shared(p);
}
__device__ __forceinline__ void cp16(char* dst, const void* src, bool v) {
    asm volatile("cp.async.cg.shared.global [%0], [%1], 16, %2;"
                 :: "r"(s2u(dst)), "l"(src), "r"(v ? 16 : 0));
}
#define CP_COMMIT() asm volatile("cp.async.commit_group;" ::: "memory")

// ---------------- mma ----------------
__device__ __forceinline__ void mma_bf16(float* c, const uint32_t* a, const uint32_t* b) {
    asm volatile(
        "mma.sync.aligned.m16n8k16.row.col.f32.bf16.bf16.f32 "
        "{%0,%1,%2,%3}, {%4,%5,%6,%7}, {%8,%9}, {%0,%1,%2,%3};"
        : "+f"(c[0]), "+f"(c[1]), "+f"(c[2]), "+f"(c[3])
        : "r"(a[0]), "r"(a[1]), "r"(a[2]), "r"(a[3]), "r"(b[0]), "r"(b[1]));
}

// ---------------- swizzles ----------------
__device__ __forceinline__ uint32_t swz128(uint32_t off) {
    return off ^ ((off >> 3) & 0x70);
}
__device__ __forceinline__ uint32_t swzkn(uint32_t row, uint32_t cb) {
    uint32_t unit = (cb >> 4) & 7;
    return row * 256 + (cb & 0x80) + ((unit ^ (row & 7)) << 4) + (cb & 15);
}
// x-slab rows of 512B: XOR 16B-unit with row%8 (within each 128B block)
__device__ __forceinline__ uint32_t swzx(uint32_t ss, uint32_t cb) {
    return ss * 512 + (cb ^ ((ss & 7) << 4));
}

// ---------------- one K=64 chunk (128x128 CTA tile, 8 warps 4x2, 32x64 warp) ----
template <bool BT>
__device__ __forceinline__ void warp_k64(const char* As, const char* Bs,
                                         float acc[16][4], int wm, int wn, int lane) {
    uint32_t abase = s2u(As), bbase = s2u(Bs);
#pragma unroll
    for (int kk = 0; kk < 4; kk++) {
        int ks = ((kk + wm) & 3) * 16;
        uint32_t a[2][4];
#pragma unroll
        for (int t = 0; t < 2; t++) {
            uint32_t row = wm * 32 + t * 16 + ((lane >> 3) & 1) * 8 + (lane & 7);
            uint32_t cb = (ks + (lane >> 4) * 8) * 2;
            uint32_t ad = abase + swz128(row * 128 + cb);
            asm volatile("ldmatrix.sync.aligned.m8n8.x4.shared.b16 {%0,%1,%2,%3},[%4];"
                         : "=r"(a[t][0]), "=r"(a[t][1]), "=r"(a[t][2]), "=r"(a[t][3])
                         : "r"(ad));
        }
        uint32_t b[8][2];
#pragma unroll
        for (int p4 = 0; p4 < 4; p4++) {
            uint32_t r0, r1, r2, r3;
            if (BT) {
                uint32_t row = ks + ((lane >> 3) & 1) * 8 + (lane & 7);
                uint32_t cb = (wn * 64 + p4 * 16 + (lane >> 4) * 8) * 2;
                uint32_t ad = bbase + swzkn(row, cb);
                asm volatile("ldmatrix.sync.aligned.m8n8.x4.trans.shared.b16 {%0,%1,%2,%3},[%4];"
                             : "=r"(r0), "=r"(r1), "=r"(r2), "=r"(r3) : "r"(ad));
            } else {
                uint32_t row = wn * 64 + p4 * 16 + (lane >> 4) * 8 + (lane & 7);
                uint32_t cb = (ks + ((lane >> 3) & 1) * 8) * 2;
                uint32_t ad = bbase + swz128(row * 128 + cb);
                asm volatile("ldmatrix.sync.aligned.m8n8.x4.shared.b16 {%0,%1,%2,%3},[%4];"
                             : "=r"(r0), "=r"(r1), "=r"(r2), "=r"(r3) : "r"(ad));
            }
            b[2 * p4][0] = r0; b[2 * p4][1] = r1;
            b[2 * p4 + 1][0] = r2; b[2 * p4 + 1][1] = r3;
        }
#pragma unroll
        for (int t = 0; t < 2; t++)
#pragma unroll
            for (int j = 0; j < 8; j++)
                mma_bf16(acc[t * 8 + j], a[t], b[j]);
    }
}

// ---------------- pipelined GEMM kernel (modes 0,1,2) ----------------
#define STAGE_BYTES 16384
#define B_SMEM_OFF  (3 * 16384)
#define SMEM_TOTAL  (6 * 16384)

template <int MODE>
__device__ __forceinline__ void load_chunk(char* smem, int s, int k0, int tid,
                                           int bx, int by, int bz) {
    char* Ab = smem + s * STAGE_BYTES;
    char* Bb = smem + B_SMEM_OFF + s * STAGE_BYTES;
    {
        int row = tid >> 1, h = tid & 1;
        const bf16* src;
        if (MODE == 0) {
            src = g_LIS + ((size_t)(bz * LL + by * 128 + row) * TWO_D + k0);
        } else if (MODE == 1) {
            src = g_S + ((size_t)(bz * LL + by * 128 + row) * LL + k0);
        } else {
            int r = by * 128 + row;
            if (k0 < 256)      src = g_LIS + ((size_t)r * TWO_D + k0);
            else if (k0 < 512) src = g_HRPq + ((size_t)r * DD + (k0 - 256));
            else               src = g_cqc + ((size_t)r * DD + (k0 - 512));
        }
#pragma unroll
        for (int j = 0; j < 4; j++) {
            uint32_t cb = h * 64 + j * 16;
            cp16(Ab + swz128((uint32_t)row * 128 + cb), src + cb / 2, true);
        }
    }
    if (MODE == 1) {
        int row = tid >> 2, q = tid & 3;
        const bf16* src = g_LIS + ((size_t)(bz * LL + k0 + row) * TWO_D + bx * 128);
#pragma unroll
        for (int j = 0; j < 4; j++) {
            uint32_t cb = q * 64 + j * 16;
            cp16(Bb + swzkn((uint32_t)row, cb), src + cb / 2, true);
        }
    } else {
        int row = tid >> 1, h = tid & 1;
        const bf16* src;
        if (MODE == 0) src = g_LIS + ((size_t)(bz * LL + bx * 128 + row) * TWO_D + k0);
        else {
            int kw = (k0 < 256) ? k0 : ((k0 < 512) ? k0 + 256 : k0 + 512);
            src = g_WmlpP + ((size_t)(bx * 128 + row) * HD + kw);
        }
#pragma unroll
        for (int j = 0; j < 4; j++) {
            uint32_t cb = h * 64 + j * 16;
            cp16(Bb + swz128((uint32_t)row * 128 + cb), src + cb / 2, true);
        }
    }
}

template <int MODE>
__global__ void __launch_bounds__(256, 2) k_gemm(bf16* __restrict__ xdst,
                                                 const float* __restrict__ biasP,
                                                 const int* __restrict__ csrc) {
    extern __shared__ char smem[];
    int tid = threadIdx.x, wid = tid >> 5, lane = tid & 31;
    int bx = blockIdx.x, by = blockIdx.y, bz = blockIdx.z;
    if (MODE == 0 && bx > by) return;
    int nch = (MODE == 0) ? 4 : (MODE == 1) ? (by + 1) * 2 : 12;
    int wm = wid >> 1, wn = wid & 1;

    float acc[16][4] = {};

    load_chunk<MODE>(smem, 0, 0, tid, bx, by, bz);  CP_COMMIT();
    load_chunk<MODE>(smem, 1, 64, tid, bx, by, bz); CP_COMMIT();

#pragma unroll 1
    for (int i = 0; i < nch; i++) {
        int s = i % 3;
        if (i == nch - 1) asm volatile("cp.async.wait_group 0;" ::: "memory");
        else              asm volatile("cp.async.wait_group 1;" ::: "memory");
        __syncthreads();
        if (i + 2 < nch) {
            load_chunk<MODE>(smem, (i + 2) % 3, (i + 2) * 64, tid, bx, by, bz);
            CP_COMMIT();
        }
        warp_k64<(MODE == 1)>(smem + s * STAGE_BYTES, smem + B_SMEM_OFF + s * STAGE_BYTES,
                              acc, wm, wn, lane);
    }

    if (MODE == 0) {
        __syncthreads();
        int* cv = (int*)smem;
        if (tid < 128) cv[tid] = csrc[bz * LL + bx * 128 + tid];
        __syncthreads();
        bf16* out = g_S + ((size_t)(bz * LL + by * 128)) * LL + bx * 128;
        float* rs = g_rowsum + (size_t)bz * LL;
        float* s1g = g_s1 + (size_t)bz * LL;
        float* pii = g_pii + (size_t)bz * LL;
#pragma unroll
        for (int t = 0; t < 2; t++) {
            int r = wm * 32 + t * 16 + (lane >> 2);
            int gi0 = by * 128 + r, gi1 = gi0 + 8;
            float s0 = 0.f, s1 = 0.f, m0 = 0.f, m1 = 0.f;
#pragma unroll
            for (int j = 0; j < 8; j++) {
                int cc = wn * 64 + j * 8 + (lane & 3) * 2;
                int gc = bx * 128 + cc;
                int cm0 = cv[cc], cm1 = cv[cc + 1];
                float* a = acc[t * 8 + j];
                float e0 = expp(a[0]), e1 = expp(a[1]);
                float e2 = expp(a[2]), e3 = expp(a[3]);
                if (gc == gi0)     pii[gi0] = e0;
                if (gc + 1 == gi0) pii[gi0] = e1;
                if (gc == gi1)     pii[gi1] = e2;
                if (gc + 1 == gi1) pii[gi1] = e3;
                float p0 = (gc < gi0)     ? e0 : 0.f;
                float p1 = (gc + 1 < gi0) ? e1 : 0.f;
                float p2 = (gc < gi1)     ? e2 : 0.f;
                float p3 = (gc + 1 < gi1) ? e3 : 0.f;
                s0 += p0 + p1; s1 += p2 + p3;
                m0 += (cm0 ? p0 : 0.f) + (cm1 ? p1 : 0.f);
                m1 += (cm0 ? p2 : 0.f) + (cm1 ? p3 : 0.f);
                *(bf162*)(out + (size_t)r * LL + cc)       = __floats2bfloat162_rn(p0, p1);
                *(bf162*)(out + (size_t)(r + 8) * LL + cc) = __floats2bfloat162_rn(p2, p3);
            }
#pragma unroll
            for (int off = 1; off <= 2; off <<= 1) {
                s0 += __shfl_xor_sync(0xffffffffu, s0, off);
                s1 += __shfl_xor_sync(0xffffffffu, s1, off);
                m0 += __shfl_xor_sync(0xffffffffu, m0, off);
                m1 += __shfl_xor_sync(0xffffffffu, m1, off);
            }
            if ((lane & 3) == 0) {
                atomicAdd(&rs[gi0], s0);
                atomicAdd(&rs[gi1], s1);
                atomicAdd(&s1g[gi0], m0);
                atomicAdd(&s1g[gi1], m1);
            }
        }
    } else if (MODE == 1) {
        bf16* out = g_HRPq + ((size_t)(bz * LL + by * 128)) * DD + bx * 128;
        const float* rs = g_rowsum + (size_t)bz * LL;
        const float* pii = g_pii + (size_t)bz * LL;
#pragma unroll
        for (int t = 0; t < 2; t++) {
            int r = wm * 32 + t * 16 + (lane >> 2);
            int gi0 = by * 128 + r, gi1 = gi0 + 8;
            float r0 = rs[gi0], r1 = rs[gi1];
            float inv0 = 1.f / (r0 + 1e-8f * (r0 + pii[gi0]));
            float inv1 = 1.f / (r1 + 1e-8f * (r1 + pii[gi1]));
#pragma unroll
            for (int j = 0; j < 8; j++) {
                int cc = wn * 64 + j * 8 + (lane & 3) * 2;
                float* a = acc[t * 8 + j];
                *(bf162*)(out + (size_t)r * DD + cc) =
                    __floats2bfloat162_rn(a[0] * inv0, a[1] * inv0);
                *(bf162*)(out + (size_t)(r + 8) * DD + cc) =
                    __floats2bfloat162_rn(a[2] * inv1, a[3] * inv1);
            }
        }
    } else {
        // MLP GLU epilogue with exact rank-2 ce fold-in
#pragma unroll
        for (int t = 0; t < 2; t++) {
            int r = wm * 32 + t * 16 + (lane >> 2);
            size_t gr0 = (size_t)(by * 128 + r);
            size_t gr1 = gr0 + 8;
            float rsa = g_rowsum[gr0], s1a = g_s1[gr0], pia = g_pii[gr0];
            float inva = 1.f / (rsa + 1e-8f * (rsa + pia));
            float al0 = (rsa - s1a) * inva, be0 = s1a * inva;
            int cr0 = csrc[gr0];
            float rsb = g_rowsum[gr1], s1b = g_s1[gr1], pib = g_pii[gr1];
            float invb = 1.f / (rsb + 1e-8f * (rsb + pib));
            float al1 = (rsb - s1b) * invb, be1 = s1b * invb;
            int cr1 = csrc[gr1];
#pragma unroll
            for (int j = 0; j < 4; j++) {
                int pc = wn * 64 + j * 8 + (lane & 3) * 2;
                int pnA = bx * 128 + pc, pnG = pnA + 32;
                float ba0 = biasP[pnA], ba1 = biasP[pnA + 1];
                float bg0 = biasP[pnG], bg1 = biasP[pnG + 1];
                float u1A0c0 = g_u1[cr0 * TWO_D + pnA], u1A1c0 = g_u1[cr0 * TWO_D + pnA + 1];
                float u1G0c0 = g_u1[cr0 * TWO_D + pnG], u1G1c0 = g_u1[cr0 * TWO_D + pnG + 1];
                float u1A0c1 = g_u1[cr1 * TWO_D + pnA], u1A1c1 = g_u1[cr1 * TWO_D + pnA + 1];
                float u1G0c1 = g_u1[cr1 * TWO_D + pnG], u1G1c1 = g_u1[cr1 * TWO_D + pnG + 1];
                float u2A00 = g_u2[pnA], u2A10 = g_u2[pnA + 1];
                float u2G00 = g_u2[pnG], u2G10 = g_u2[pnG + 1];
                float u2A01 = g_u2[TWO_D + pnA], u2A11 = g_u2[TWO_D + pnA + 1];
                float u2G01 = g_u2[TWO_D + pnG], u2G11 = g_u2[TWO_D + pnG + 1];
                float aA0r0 = u1A0c0 + al0 * u2A00 + be0 * u2A01;
                float aA1r0 = u1A1c0 + al0 * u2A10 + be0 * u2A11;
                float aG0r0 = u1G0c0 + al0 * u2G00 + be0 * u2G01;
                float aG1r0 = u1G1c0 + al0 * u2G10 + be0 * u2G11;
                float aA0r1 = u1A0c1 + al1 * u2A00 + be1 * u2A01;
                float aA1r1 = u1A1c1 + al1 * u2A10 + be1 * u2A11;
                float aG0r1 = u1G0c1 + al1 * u2G00 + be1 * u2G01;
                float aG1r1 = u1G1c1 + al1 * u2G10 + be1 * u2G11;
                float* a = acc[t * 8 + j];
                float* g = acc[t * 8 + j + 4];
                int ocol = (bx * 2 + wn) * 32 + j * 8 + (lane & 3) * 2;
                float v0 = (a[0] + ba0 + aA0r0) * sigmoidf_(g[0] + bg0 + aG0r0);
                float v1 = (a[1] + ba1 + aA1r0) * sigmoidf_(g[1] + bg1 + aG1r0);
                float v2 = (a[2] + ba0 + aA0r1) * sigmoidf_(g[2] + bg0 + aG0r1);
                float v3 = (a[3] + ba1 + aA1r1) * sigmoidf_(g[3] + bg1 + aG1r1);
                *(bf162*)(xdst + gr0 * DD + ocol) = __floats2bfloat162_rn(v0, v1);
                *(bf162*)(xdst + gr1 * DD + ocol) = __floats2bfloat162_rn(v2, v3);
            }
        }
    }
}

// ---------------- conv kernel: resident x slab + 2-stage B pipeline ----------------
// smem: [0, 67584) x slab: 131 rows (x rows by*128-3 .. by*128+127) x 512B, swzx.
//       [67584, 67584+2*16384) B double buffer (mk layout 128x128B, swz128).
#define XSLAB_BYTES 67584
#define CONV_B_OFF  XSLAB_BYTES
#define CONV_SMEM   (XSLAB_BYTES + 2 * 16384)

__device__ __forceinline__ void load_convB(char* smem, int s, int k0, int tid,
                                           int bx, int layer) {
    char* Bb = smem + CONV_B_OFF + s * 16384;
    int row = tid >> 1, h = tid & 1;
    const bf16* src = g_convwP + ((size_t)(layer * TWO_D + bx * 128 + row)) * 1024 + k0;
#pragma unroll
    for (int j = 0; j < 4; j++) {
        uint32_t cb = h * 64 + j * 16;
        cp16(Bb + swz128((uint32_t)row * 128 + cb), src + cb / 2, true);
    }
}

__global__ void __launch_bounds__(256, 2) k_conv(const bf16* __restrict__ xsrc,
                                                 bf16* __restrict__ xdst,
                                                 const float* __restrict__ biasP,
                                                 int layer) {
    extern __shared__ char smem[];
    int tid = threadIdx.x, wid = tid >> 5, lane = tid & 31;
    int bx = blockIdx.x, by = blockIdx.y, bz = blockIdx.z;
    int wm = wid >> 1, wn = wid & 1;

    // load resident x slab: 131 rows x 32 x 16B
#pragma unroll
    for (int it = 0; it < 17; it++) {
        int idx = it * 256 + tid;
        if (idx < 131 * 32) {
            int ss = idx >> 5, c16 = idx & 31;
            int grow = by * 128 + ss - 3;
            bool v = (grow >= 0);
            const bf16* src = xsrc + ((size_t)bz * LL + (v ? grow : 0)) * DD + c16 * 8;
            cp16(smem + swzx((uint32_t)ss, (uint32_t)c16 * 16), src, v);
        }
    }
    load_convB(smem, 0, 0, tid, bx, layer);  CP_COMMIT();
    load_convB(smem, 1, 64, tid, bx, layer); CP_COMMIT();

    float acc[16][4] = {};
    uint32_t xbase = s2u(smem);

#pragma unroll 1
    for (int i = 0; i < 16; i++) {
        if (i == 15) asm volatile("cp.async.wait_group 0;" ::: "memory");
        else         asm volatile("cp.async.wait_group 1;" ::: "memory");
        __syncthreads();
        int tap = i >> 2, d0 = (i & 3) * 64;
        uint32_t bbase = s2u(smem + CONV_B_OFF + (i & 1) * 16384);
#pragma unroll
        for (int kk = 0; kk < 4; kk++) {
            int ks = ((kk + wm) & 3) * 16;
            uint32_t a[2][4];
#pragma unroll
            for (int t = 0; t < 2; t++) {
                uint32_t row = wm * 32 + t * 16 + ((lane >> 3) & 1) * 8 + (lane & 7);
                uint32_t ss = row + tap;
                uint32_t cb = (d0 + ks + (lane >> 4) * 8) * 2;
                uint32_t ad = xbase + swzx(ss, cb);
                asm volatile("ldmatrix.sync.aligned.m8n8.x4.shared.b16 {%0,%1,%2,%3},[%4];"
                             : "=r"(a[t][0]), "=r"(a[t][1]), "=r"(a[t][2]), "=r"(a[t][3])
                             : "r"(ad));
            }
            uint32_t b[8][2];
#pragma unroll
            for (int p4 = 0; p4 < 4; p4++) {
                uint32_t r0, r1, r2, r3;
                uint32_t row = wn * 64 + p4 * 16 + (lane >> 4) * 8 + (lane & 7);
                uint32_t cb = (ks + ((lane >> 3) & 1) * 8) * 2;
                uint32_t ad = bbase + swz128(row * 128 + cb);
                asm volatile("ldmatrix.sync.aligned.m8n8.x4.shared.b16 {%0,%1,%2,%3},[%4];"
                             : "=r"(r0), "=r"(r1), "=r"(r2), "=r"(r3) : "r"(ad));
                b[2 * p4][0] = r0; b[2 * p4][1] = r1;
                b[2 * p4 + 1][0] = r2; b[2 * p4 + 1][1] = r3;
            }
#pragma unroll
            for (int t = 0; t < 2; t++)
#pragma unroll
                for (int j = 0; j < 8; j++)
                    mma_bf16(acc[t * 8 + j], a[t], b[j]);
        }
        __syncthreads();
        if (i + 2 < 16) { load_convB(smem, i & 1, (i + 2) * 64, tid, bx, layer); CP_COMMIT(); }
    }

    // GLU + residual epilogue (residual read from resident x slab: row r -> ss=r+3)
#pragma unroll
    for (int t = 0; t < 2; t++) {
        int r = wm * 32 + t * 16 + (lane >> 2);
        size_t gr0 = (size_t)bz * LL + by * 128 + r;
        size_t gr1 = gr0 + 8;
#pragma unroll
        for (int j = 0; j < 4; j++) {
            int pc = wn * 64 + j * 8 + (lane & 3) * 2;
            int pnA = bx * 128 + pc, pnG = pnA + 32;
            float ba0 = biasP[pnA], ba1 = biasP[pnA + 1];
            float bg0 = biasP[pnG], bg1 = biasP[pnG + 1];
            float* a = acc[t * 8 + j];
            float* g = acc[t * 8 + j + 4];
            int ocol = (bx * 2 + wn) * 32 + j * 8 + (lane & 3) * 2;
            float v0 = (a[0] + ba0) * sigmoidf_(g[0] + bg0);
            float v1 = (a[1] + ba1) * sigmoidf_(g[1] + bg1);
            float v2 = (a[2] + ba0) * sigmoidf_(g[2] + bg0);
            float v3 = (a[3] + ba1) * sigmoidf_(g[3] + bg1);
            uint32_t ss0 = (uint32_t)r + 3, ss1 = ss0 + 8;
            bf162 r0 = *(bf162*)(smem + swzx(ss0, (uint32_t)ocol * 2));
            bf162 r1 = *(bf162*)(smem + swzx(ss1, (uint32_t)ocol * 2));
            v0 += __bfloat162float(r0.x); v1 += __bfloat162float(r0.y);
            v2 += __bfloat162float(r1.x); v3 += __bfloat162float(r1.y);
            *(bf162*)(xdst + gr0 * DD + ocol) = __floats2bfloat162_rn(v0, v1);
            *(bf162*)(xdst + gr1 * DD + ocol) = __floats2bfloat162_rn(v2, v3);
        }
    }
}

// ---------------- prep A: zero sums + embed ----------------
#define PA0 256
#define PA1 (PA0 + 65536)
__global__ __launch_bounds__(256) void k_prep_embed(const int* __restrict__ q,
                                                    const int* __restrict__ c,
                                                    const float* __restrict__ Eq,
                                                    const float* __restrict__ Ec) {
    int bid = blockIdx.x, tid = threadIdx.x;
    if (bid < PA0) {
        int id = bid * 256 + tid;
        g_rowsum[id] = 0.f;
        g_s1[id] = 0.f;
    } else {
        int r = bid - PA0, d = tid;
        int qi = q[r], ci = c[r];
        g_LIS[(size_t)r * TWO_D + d]      = __float2bfloat16(Eq[(size_t)qi * DD + d]);
        g_LIS[(size_t)r * TWO_D + DD + d] = __float2bfloat16(Ec[(size_t)ci * DD + d]);
    }
}

// ---------------- prep B: weights/u/cqc (side stream) ----------------
#define PB0 2560
#define PB2 (PB0 + 2)
#define PBU (PB2 + 8)
#define PB3 (PBU + 768)
#define PB4 (PB3 + 16384)
__global__ __launch_bounds__(256) void k_prep_rest(const float* __restrict__ W1w,
                                                   const float* __restrict__ W2w,
                                                   const float* __restrict__ b1,
                                                   const float* __restrict__ b2,
                                                   const float* __restrict__ convb,
                                                   const float* __restrict__ convw,
                                                   const float* __restrict__ cqc,
                                                   const float* __restrict__ Ec) {
    __shared__ bf16 tile[64][40];
    int bid = blockIdx.x, tid = threadIdx.x;
    if (bid < PB0) {
        int id = bid * 256 + tid;
        if (id < TWO_D * HD) {
            int pn = id / HD, k = id % HD;
            int n = unpackN64(pn);
            float v = (n < DD) ? W1w[(size_t)n * HD + k] : W2w[(size_t)(n - DD) * HD + k];
            g_WmlpP[id] = __float2bfloat16(v);
        }
    } else if (bid < PB2) {
        int pn = (bid - PB0) * 256 + tid;
        int n = unpackN64(pn);
        g_bP[pn] = (n < DD) ? b1[n] : b2[n - DD];
        for (int l = 0; l < 3; l++)
            g_bconvP[l * TWO_D + pn] = convb[l * TWO_D + n];
    } else if (bid < PBU) {
        int t = (bid - PB2) * 256 + tid;
        int table = t >> 10;
        int rem = t & 1023;
        int e = rem >> 9, pn = rem & 511;
        int n = unpackN64(pn);
        const float* wr = (n < DD) ? (W1w + (size_t)n * HD) : (W2w + (size_t)(n - DD) * HD);
        int ko = table ? 768 : 256;
        const float* ec = Ec + e * DD;
        float s = 0.f;
        for (int k = 0; k < DD; k++) s += ec[k] * wr[ko + k];
        if (table == 0) g_u1[e * TWO_D + pn] = s;
        else            g_u2[e * TWO_D + pn] = s;
    } else if (bid < PB3) {
        int id = bid - PBU;
        int kx = id & 15, ny = (id >> 4) & 15, l = id >> 8;
        int k0 = kx * 64, n0 = ny * 32;
        {
            int row = tid >> 2, seg = tid & 3;
            const float* src = convw + ((size_t)(l * 1024 + k0 + row)) * TWO_D + n0 + seg * 8;
            float4 v0 = *(const float4*)src;
            float4 v1 = *(const float4*)(src + 4);
            tile[row][seg * 8 + 0] = __float2bfloat16(v0.x);
            tile[row][seg * 8 + 1] = __float2bfloat16(v0.y);
            tile[row][seg * 8 + 2] = __float2bfloat16(v0.z);
            tile[row][seg * 8 + 3] = __float2bfloat16(v0.w);
            tile[row][seg * 8 + 4] = __float2bfloat16(v1.x);
            tile[row][seg * 8 + 5] = __float2bfloat16(v1.y);
            tile[row][seg * 8 + 6] = __float2bfloat16(v1.z);
            tile[row][seg * 8 + 7] = __float2bfloat16(v1.w);
        }
        __syncthreads();
        {
            int s = (n0 < 256) ? (n0 >> 5) : ((n0 - 256) >> 5);
            int pn0 = s * 64 + ((n0 < 256) ? 0 : 32);
            int row = tid >> 3, seg = tid & 7;
            bf16 buf[8];
#pragma unroll
            for (int j = 0; j < 8; j++) buf[j] = tile[seg * 8 + j][row];
            bf16* dst = g_convwP + ((size_t)(l * TWO_D + pn0 + row)) * 1024 + k0 + seg * 8;
            *(uint4*)dst = *(uint4*)buf;
        }
    } else {
        size_t id = (size_t)(bid - PB3) * 256 + tid;
        float4 v = ((const float4*)cqc)[id];
        bf162* o = (bf162*)g_cqc;
        o[id * 2] = __floats2bfloat162_rn(v.x, v.y);
        o[id * 2 + 1] = __floats2bfloat162_rn(v.z, v.w);
    }
}

// ---------------- predict ----------------
__global__ __launch_bounds__(256) void k_predict(const bf16* __restrict__ xf,
                                                 float* __restrict__ out) {
    int warp = threadIdx.x >> 5, lane = threadIdx.x & 31;
    int o = blockIdx.x * 8 + warp;
    if (o >= BB * (LL - 1)) return;
    int b = o / (LL - 1), l = o % (LL - 1);
    const bf16* xr = xf + (size_t)(b * LL + l) * DD;
    const bf16* qr = g_LIS + (size_t)(b * LL + l + 1) * TWO_D;
    float s = 0.f;
    for (int d = lane; d < DD; d += 32)
        s += __bfloat162float(xr[d]) * __bfloat162float(qr[d]);
#pragma unroll
    for (int off = 16; off > 0; off >>= 1) s += __shfl_down_sync(0xffffffffu, s, off);
    if (lane == 0) out[o] = sigmoidf_(s);
}

static bf16* addr_x() { void* p; cudaGetSymbolAddress(&p, g_x); return (bf16*)p; }
static bf16* addr_x2() { void* p; cudaGetSymbolAddress(&p, g_x2); return (bf16*)p; }
static float* addr_bP() { void* p; cudaGetSymbolAddress(&p, g_bP); return (float*)p; }
static float* addr_bconvP() { void* p; cudaGetSymbolAddress(&p, g_bconvP); return (float*)p; }

// ---------------- launch ----------------
extern "C" void kernel_launch(void* const* d_in, const int* in_sizes, int n_in,
                              void* d_out, int out_size) {
    (void)in_sizes; (void)n_in; (void)out_size;
    const int*   q     = (const int*)d_in[0];
    const int*   c     = (const int*)d_in[1];
    const float* cqc   = (const float*)d_in[2];
    const float* Eq    = (const float*)d_in[3];
    const float* Ec    = (const float*)d_in[4];
    const float* W1w   = (const float*)d_in[5];
    const float* W1b   = (const float*)d_in[6];
    const float* W2w   = (const float*)d_in[7];
    const float* W2b   = (const float*)d_in[8];
    const float* convw = (const float*)d_in[9];
    const float* convb = (const float*)d_in[10];
    float* out = (float*)d_out;

    static bf16 *xA = nullptr, *xB = nullptr;
    static float *bP = nullptr, *bconvP = nullptr;
    static cudaStream_t s2;
    static cudaEvent_t evF, evJ;
    static bool init_done = false;
    if (!init_done) {
        cudaFuncSetAttribute(k_gemm<0>, cudaFuncAttributeMaxDynamicSharedMemorySize, SMEM_TOTAL);
        cudaFuncSetAttribute(k_gemm<1>, cudaFuncAttributeMaxDynamicSharedMemorySize, SMEM_TOTAL);
        cudaFuncSetAttribute(k_gemm<2>, cudaFuncAttributeMaxDynamicSharedMemorySize, SMEM_TOTAL);
        cudaFuncSetAttribute(k_conv, cudaFuncAttributeMaxDynamicSharedMemorySize, CONV_SMEM);
        xA = addr_x(); xB = addr_x2();
        bP = addr_bP(); bconvP = addr_bconvP();
        cudaStreamCreateWithFlags(&s2, cudaStreamNonBlocking);
        cudaEventCreateWithFlags(&evF, cudaEventDisableTiming);
        cudaEventCreateWithFlags(&evJ, cudaEventDisableTiming);
        init_done = true;
    }

    cudaEventRecord(evF, 0);
    cudaStreamWaitEvent(s2, evF, 0);
    k_prep_rest<<<PB4, 256, 0, s2>>>(W1w, W2w, W1b, W2b, convb, convw, cqc, Ec);
    cudaEventRecord(evJ, s2);

    k_prep_embed<<<PA1, 256>>>(q, c, Eq, Ec);
    k_gemm<0><<<dim3(8, 8, BB), 256, SMEM_TOTAL>>>(nullptr, nullptr, c);
    k_gemm<1><<<dim3(2, 8, BB), 256, SMEM_TOTAL>>>(nullptr, nullptr, nullptr);

    cudaStreamWaitEvent(0, evJ, 0);
    k_gemm<2><<<dim3(4, 512, 1), 256, SMEM_TOTAL>>>(xA, bP, c);
    bf16* src = xA;
    bf16* dst = xB;
    for (int l = 0; l < 3; l++) {
        k_conv<<<dim3(4, 8, BB), 256, CONV_SMEM>>>(src, dst, bconvP + l * TWO_D, l);
        bf16* t = src; src = dst; dst = t;
    }
    k_predict<<<(BB * (LL - 1) + 7) / 8, 256>>>(src, out);
}

// round 17
// speedup vs baseline: 1.1518x; 1.0035x over previous
#include <cuda_runtime.h>
#include <cuda_bf16.h>
#include <math.h>
#include <stdint.h>

#define BB 64
#define LL 1024
#define DD 256
#define TWO_D 512
#define HD 1280

typedef __nv_bfloat16 bf16;
typedef __nv_bfloat162 bf162;

// ---------------- scratch (device globals) ----------------
__device__ bf16 g_LIS[(size_t)BB * LL * TWO_D];
__device__ bf16 g_S[(size_t)BB * LL * LL];
__device__ bf16 g_HRPq[(size_t)BB * LL * DD];
__device__ bf16 g_x[(size_t)BB * LL * DD];
__device__ bf16 g_x2[(size_t)BB * LL * DD];
__device__ bf16 g_cqc[(size_t)BB * LL * DD];
__device__ bf16 g_WmlpP[(size_t)TWO_D * HD];
__device__ float g_bP[TWO_D];
__device__ bf16 g_convwP[(size_t)3 * TWO_D * 1024];
__device__ float g_bconvP[3 * TWO_D];
__device__ float g_rowsum[(size_t)BB * LL];
__device__ float g_s1[(size_t)BB * LL];
__device__ float g_pii[(size_t)BB * LL];
__device__ float g_u1[2 * TWO_D];
__device__ float g_u2[2 * TWO_D];

__device__ __forceinline__ float sigmoidf_(float v) { return 1.f / (1.f + __expf(-v)); }

__device__ __forceinline__ float expp(float x) {
    float e = fmaf(x, 0.00833333f, 0.04166667f);
    e = fmaf(x, e, 0.16666667f);
    e = fmaf(x, e, 0.5f);
    e = fmaf(x, e, 1.0f);
    e = fmaf(x, e, 1.0f);
    if (fabsf(x) > 0.5f) e = __expf(x);
    return e;
}

__device__ __forceinline__ int unpackN64(int pn) {
    int s = pn >> 6, c = pn & 63;
    return (c < 32) ? s * 32 + c : 256 + s * 32 + (c - 32);
}

// ---------------- async copy ----------------
__device__ __forceinline__ uint32_t s2u(const void* p) {
    return (uint32_t)__cvta_generic_to_shared(p);
}
__device__ __forceinline__ void cp16(char* dst, const void* src, bool v) {
    asm volatile("cp.async.cg.shared.global [%0], [%1], 16, %2;"
                 :: "r"(s2u(dst)), "l"(src), "r"(v ? 16 : 0));
}
#define CP_COMMIT() asm volatile("cp.async.commit_group;" ::: "memory")

// ---------------- mma ----------------
__device__ __forceinline__ void mma_bf16(float* c, const uint32_t* a, const uint32_t* b) {
    asm volatile(
        "mma.sync.aligned.m16n8k16.row.col.f32.bf16.bf16.f32 "
        "{%0,%1,%2,%3}, {%4,%5,%6,%7}, {%8,%9}, {%0,%1,%2,%3};"
        : "+f"(c[0]), "+f"(c[1]), "+f"(c[2]), "+f"(c[3])
        : "r"(a[0]), "r"(a[1]), "r"(a[2]), "r"(a[3]), "r"(b[0]), "r"(b[1]));
}

// ---------------- swizzles ----------------
__device__ __forceinline__ uint32_t swz128(uint32_t off) {
    return off ^ ((off >> 3) & 0x70);
}
__device__ __forceinline__ uint32_t swzkn(uint32_t row, uint32_t cb) {
    uint32_t unit = (cb >> 4) & 7;
    return row * 256 + (cb & 0x80) + ((unit ^ (row & 7)) << 4) + (cb & 15);
}
__device__ __forceinline__ uint32_t swzx(uint32_t ss, uint32_t cb) {
    return ss * 512 + (cb ^ ((ss & 7) << 4));
}

// ---------------- one K=64 chunk (128x128 CTA tile, 8 warps 4x2, 32x64 warp) ----
template <bool BT>
__device__ __forceinline__ void warp_k64(const char* As, const char* Bs,
                                         float acc[16][4], int wm, int wn, int lane) {
    uint32_t abase = s2u(As), bbase = s2u(Bs);
#pragma unroll
    for (int kk = 0; kk < 4; kk++) {
        int ks = ((kk + wm) & 3) * 16;
        uint32_t a[2][4];
#pragma unroll
        for (int t = 0; t < 2; t++) {
            uint32_t row = wm * 32 + t * 16 + ((lane >> 3) & 1) * 8 + (lane & 7);
            uint32_t cb = (ks + (lane >> 4) * 8) * 2;
            uint32_t ad = abase + swz128(row * 128 + cb);
            asm volatile("ldmatrix.sync.aligned.m8n8.x4.shared.b16 {%0,%1,%2,%3},[%4];"
                         : "=r"(a[t][0]), "=r"(a[t][1]), "=r"(a[t][2]), "=r"(a[t][3])
                         : "r"(ad));
        }
        uint32_t b[8][2];
#pragma unroll
        for (int p4 = 0; p4 < 4; p4++) {
            uint32_t r0, r1, r2, r3;
            if (BT) {
                uint32_t row = ks + ((lane >> 3) & 1) * 8 + (lane & 7);
                uint32_t cb = (wn * 64 + p4 * 16 + (lane >> 4) * 8) * 2;
                uint32_t ad = bbase + swzkn(row, cb);
                asm volatile("ldmatrix.sync.aligned.m8n8.x4.trans.shared.b16 {%0,%1,%2,%3},[%4];"
                             : "=r"(r0), "=r"(r1), "=r"(r2), "=r"(r3) : "r"(ad));
            } else {
                uint32_t row = wn * 64 + p4 * 16 + (lane >> 4) * 8 + (lane & 7);
                uint32_t cb = (ks + ((lane >> 3) & 1) * 8) * 2;
                uint32_t ad = bbase + swz128(row * 128 + cb);
                asm volatile("ldmatrix.sync.aligned.m8n8.x4.shared.b16 {%0,%1,%2,%3},[%4];"
                             : "=r"(r0), "=r"(r1), "=r"(r2), "=r"(r3) : "r"(ad));
            }
            b[2 * p4][0] = r0; b[2 * p4][1] = r1;
            b[2 * p4 + 1][0] = r2; b[2 * p4 + 1][1] = r3;
        }
#pragma unroll
        for (int t = 0; t < 2; t++)
#pragma unroll
            for (int j = 0; j < 8; j++)
                mma_bf16(acc[t * 8 + j], a[t], b[j]);
    }
}

// ---------------- pipelined GEMM kernel (modes 0,1,2) ----------------
#define STAGE_BYTES 16384
#define B_SMEM_OFF  (3 * 16384)
#define SMEM_TOTAL  (6 * 16384)

template <int MODE>
__device__ __forceinline__ void load_chunk(char* smem, int s, int k0, int tid,
                                           int bx, int by, int bz, bool skipB) {
    char* Ab = smem + s * STAGE_BYTES;
    char* Bb = smem + B_SMEM_OFF + s * STAGE_BYTES;
    {
        int row = tid >> 1, h = tid & 1;
        const bf16* src;
        if (MODE == 0) {
            src = g_LIS + ((size_t)(bz * LL + by * 128 + row) * TWO_D + k0);
        } else if (MODE == 1) {
            src = g_S + ((size_t)(bz * LL + by * 128 + row) * LL + k0);
        } else {
            int r = by * 128 + row;
            if (k0 < 256)      src = g_LIS + ((size_t)r * TWO_D + k0);
            else if (k0 < 512) src = g_HRPq + ((size_t)r * DD + (k0 - 256));
            else               src = g_cqc + ((size_t)r * DD + (k0 - 512));
        }
#pragma unroll
        for (int j = 0; j < 4; j++) {
            uint32_t cb = h * 64 + j * 16;
            cp16(Ab + swz128((uint32_t)row * 128 + cb), src + cb / 2, true);
        }
    }
    if (skipB) return;
    if (MODE == 1) {
        int row = tid >> 2, q = tid & 3;
        const bf16* src = g_LIS + ((size_t)(bz * LL + k0 + row) * TWO_D + bx * 128);
#pragma unroll
        for (int j = 0; j < 4; j++) {
            uint32_t cb = q * 64 + j * 16;
            cp16(Bb + swzkn((uint32_t)row, cb), src + cb / 2, true);
        }
    } else {
        int row = tid >> 1, h = tid & 1;
        const bf16* src;
        if (MODE == 0) src = g_LIS + ((size_t)(bz * LL + bx * 128 + row) * TWO_D + k0);
        else {
            int kw = (k0 < 256) ? k0 : ((k0 < 512) ? k0 + 256 : k0 + 512);
            src = g_WmlpP + ((size_t)(bx * 128 + row) * HD + kw);
        }
#pragma unroll
        for (int j = 0; j < 4; j++) {
            uint32_t cb = h * 64 + j * 16;
            cp16(Bb + swz128((uint32_t)row * 128 + cb), src + cb / 2, true);
        }
    }
}

template <int MODE>
__global__ void __launch_bounds__(256, 2) k_gemm(bf16* __restrict__ xdst,
                                                 const float* __restrict__ biasP,
                                                 const int* __restrict__ csrc) {
    extern __shared__ char smem[];
    int tid = threadIdx.x, wid = tid >> 5, lane = tid & 31;
    int bx = blockIdx.x, bz = blockIdx.z;
    int by = (MODE == 1) ? (7 - blockIdx.y) : blockIdx.y;   // hrp: heavy CTAs first
    if (MODE == 0 && bx > by) return;
    bool diag = (MODE == 0) && (bx == by);
    int nch = (MODE == 0) ? 4 : (MODE == 1) ? (by + 1) * 2 : 12;
    int wm = wid >> 1, wn = wid & 1;

    float acc[16][4] = {};

    load_chunk<MODE>(smem, 0, 0, tid, bx, by, bz, diag);  CP_COMMIT();
    load_chunk<MODE>(smem, 1, 64, tid, bx, by, bz, diag); CP_COMMIT();

#pragma unroll 1
    for (int i = 0; i < nch; i++) {
        int s = i % 3;
        if (i == nch - 1) asm volatile("cp.async.wait_group 0;" ::: "memory");
        else              asm volatile("cp.async.wait_group 1;" ::: "memory");
        __syncthreads();
        if (i + 2 < nch) {
            load_chunk<MODE>(smem, (i + 2) % 3, (i + 2) * 64, tid, bx, by, bz, diag);
            CP_COMMIT();
        }
        const char* Bp = diag ? (smem + s * STAGE_BYTES)
                              : (smem + B_SMEM_OFF + s * STAGE_BYTES);
        warp_k64<(MODE == 1)>(smem + s * STAGE_BYTES, Bp, acc, wm, wn, lane);
    }

    if (MODE == 0) {
        __syncthreads();
        int* cv = (int*)smem;
        if (tid < 128) cv[tid] = csrc[bz * LL + bx * 128 + tid];
        __syncthreads();
        bf16* out = g_S + ((size_t)(bz * LL + by * 128)) * LL + bx * 128;
        float* rs = g_rowsum + (size_t)bz * LL;
        float* s1g = g_s1 + (size_t)bz * LL;
        float* pii = g_pii + (size_t)bz * LL;
#pragma unroll
        for (int t = 0; t < 2; t++) {
            int r = wm * 32 + t * 16 + (lane >> 2);
            int gi0 = by * 128 + r, gi1 = gi0 + 8;
            float s0 = 0.f, s1 = 0.f, m0 = 0.f, m1 = 0.f;
#pragma unroll
            for (int j = 0; j < 8; j++) {
                int cc = wn * 64 + j * 8 + (lane & 3) * 2;
                int gc = bx * 128 + cc;
                int cm0 = cv[cc], cm1 = cv[cc + 1];
                float* a = acc[t * 8 + j];
                float e0 = expp(a[0]), e1 = expp(a[1]);
                float e2 = expp(a[2]), e3 = expp(a[3]);
                if (gc == gi0)     pii[gi0] = e0;
                if (gc + 1 == gi0) pii[gi0] = e1;
                if (gc == gi1)     pii[gi1] = e2;
                if (gc + 1 == gi1) pii[gi1] = e3;
                float p0 = (gc < gi0)     ? e0 : 0.f;
                float p1 = (gc + 1 < gi0) ? e1 : 0.f;
                float p2 = (gc < gi1)     ? e2 : 0.f;
                float p3 = (gc + 1 < gi1) ? e3 : 0.f;
                s0 += p0 + p1; s1 += p2 + p3;
                m0 += (cm0 ? p0 : 0.f) + (cm1 ? p1 : 0.f);
                m1 += (cm0 ? p2 : 0.f) + (cm1 ? p3 : 0.f);
                *(bf162*)(out + (size_t)r * LL + cc)       = __floats2bfloat162_rn(p0, p1);
                *(bf162*)(out + (size_t)(r + 8) * LL + cc) = __floats2bfloat162_rn(p2, p3);
            }
#pragma unroll
            for (int off = 1; off <= 2; off <<= 1) {
                s0 += __shfl_xor_sync(0xffffffffu, s0, off);
                s1 += __shfl_xor_sync(0xffffffffu, s1, off);
                m0 += __shfl_xor_sync(0xffffffffu, m0, off);
                m1 += __shfl_xor_sync(0xffffffffu, m1, off);
            }
            if ((lane & 3) == 0) {
                atomicAdd(&rs[gi0], s0);
                atomicAdd(&rs[gi1], s1);
                atomicAdd(&s1g[gi0], m0);
                atomicAdd(&s1g[gi1], m1);
            }
        }
    } else if (MODE == 1) {
        bf16* out = g_HRPq + ((size_t)(bz * LL + by * 128)) * DD + bx * 128;
        const float* rs = g_rowsum + (size_t)bz * LL;
        const float* pii = g_pii + (size_t)bz * LL;
#pragma unroll
        for (int t = 0; t < 2; t++) {
            int r = wm * 32 + t * 16 + (lane >> 2);
            int gi0 = by * 128 + r, gi1 = gi0 + 8;
            float r0 = rs[gi0], r1 = rs[gi1];
            float inv0 = 1.f / (r0 + 1e-8f * (r0 + pii[gi0]));
            float inv1 = 1.f / (r1 + 1e-8f * (r1 + pii[gi1]));
#pragma unroll
            for (int j = 0; j < 8; j++) {
                int cc = wn * 64 + j * 8 + (lane & 3) * 2;
                float* a = acc[t * 8 + j];
                *(bf162*)(out + (size_t)r * DD + cc) =
                    __floats2bfloat162_rn(a[0] * inv0, a[1] * inv0);
                *(bf162*)(out + (size_t)(r + 8) * DD + cc) =
                    __floats2bfloat162_rn(a[2] * inv1, a[3] * inv1);
            }
        }
    } else {
        // MLP GLU epilogue with exact rank-2 ce fold-in
#pragma unroll
        for (int t = 0; t < 2; t++) {
            int r = wm * 32 + t * 16 + (lane >> 2);
            size_t gr0 = (size_t)(by * 128 + r);
            size_t gr1 = gr0 + 8;
            float rsa = g_rowsum[gr0], s1a = g_s1[gr0], pia = g_pii[gr0];
            float inva = 1.f / (rsa + 1e-8f * (rsa + pia));
            float al0 = (rsa - s1a) * inva, be0 = s1a * inva;
            int cr0 = csrc[gr0];
            float rsb = g_rowsum[gr1], s1b = g_s1[gr1], pib = g_pii[gr1];
            float invb = 1.f / (rsb + 1e-8f * (rsb + pib));
            float al1 = (rsb - s1b) * invb, be1 = s1b * invb;
            int cr1 = csrc[gr1];
#pragma unroll
            for (int j = 0; j < 4; j++) {
                int pc = wn * 64 + j * 8 + (lane & 3) * 2;
                int pnA = bx * 128 + pc, pnG = pnA + 32;
                float ba0 = biasP[pnA], ba1 = biasP[pnA + 1];
                float bg0 = biasP[pnG], bg1 = biasP[pnG + 1];
                float u1A0c0 = g_u1[cr0 * TWO_D + pnA], u1A1c0 = g_u1[cr0 * TWO_D + pnA + 1];
                float u1G0c0 = g_u1[cr0 * TWO_D + pnG], u1G1c0 = g_u1[cr0 * TWO_D + pnG + 1];
                float u1A0c1 = g_u1[cr1 * TWO_D + pnA], u1A1c1 = g_u1[cr1 * TWO_D + pnA + 1];
                float u1G0c1 = g_u1[cr1 * TWO_D + pnG], u1G1c1 = g_u1[cr1 * TWO_D + pnG + 1];
                float u2A00 = g_u2[pnA], u2A10 = g_u2[pnA + 1];
                float u2G00 = g_u2[pnG], u2G10 = g_u2[pnG + 1];
                float u2A01 = g_u2[TWO_D + pnA], u2A11 = g_u2[TWO_D + pnA + 1];
                float u2G01 = g_u2[TWO_D + pnG], u2G11 = g_u2[TWO_D + pnG + 1];
                float aA0r0 = u1A0c0 + al0 * u2A00 + be0 * u2A01;
                float aA1r0 = u1A1c0 + al0 * u2A10 + be0 * u2A11;
                float aG0r0 = u1G0c0 + al0 * u2G00 + be0 * u2G01;
                float aG1r0 = u1G1c0 + al0 * u2G10 + be0 * u2G11;
                float aA0r1 = u1A0c1 + al1 * u2A00 + be1 * u2A01;
                float aA1r1 = u1A1c1 + al1 * u2A10 + be1 * u2A11;
                float aG0r1 = u1G0c1 + al1 * u2G00 + be1 * u2G01;
                float aG1r1 = u1G1c1 + al1 * u2G10 + be1 * u2G11;
                float* a = acc[t * 8 + j];
                float* g = acc[t * 8 + j + 4];
                int ocol = (bx * 2 + wn) * 32 + j * 8 + (lane & 3) * 2;
                float v0 = (a[0] + ba0 + aA0r0) * sigmoidf_(g[0] + bg0 + aG0r0);
                float v1 = (a[1] + ba1 + aA1r0) * sigmoidf_(g[1] + bg1 + aG1r0);
                float v2 = (a[2] + ba0 + aA0r1) * sigmoidf_(g[2] + bg0 + aG0r1);
                float v3 = (a[3] + ba1 + aA1r1) * sigmoidf_(g[3] + bg1 + aG1r1);
                *(bf162*)(xdst + gr0 * DD + ocol) = __floats2bfloat162_rn(v0, v1);
                *(bf162*)(xdst + gr1 * DD + ocol) = __floats2bfloat162_rn(v2, v3);
            }
        }
    }
}

// ---------------- conv kernel: resident x slab + 2-stage B, 1 barrier/chunk ----
#define XSLAB_BYTES 67584
#define CONV_B_OFF  XSLAB_BYTES
#define CONV_SMEM   (XSLAB_BYTES + 2 * 16384)

__device__ __forceinline__ void load_convB(char* smem, int s, int k0, int tid,
                                           int bx, int layer) {
    char* Bb = smem + CONV_B_OFF + s * 16384;
    int row = tid >> 1, h = tid & 1;
    const bf16* src = g_convwP + ((size_t)(layer * TWO_D + bx * 128 + row)) * 1024 + k0;
#pragma unroll
    for (int j = 0; j < 4; j++) {
        uint32_t cb = h * 64 + j * 16;
        cp16(Bb + swz128((uint32_t)row * 128 + cb), src + cb / 2, true);
    }
}

__global__ void __launch_bounds__(256, 2) k_conv(const bf16* __restrict__ xsrc,
                                                 bf16* __restrict__ xdst,
                                                 const float* __restrict__ biasP,
                                                 int layer) {
    extern __shared__ char smem[];
    int tid = threadIdx.x, wid = tid >> 5, lane = tid & 31;
    int bx = blockIdx.x, by = blockIdx.y, bz = blockIdx.z;
    int wm = wid >> 1, wn = wid & 1;

    // resident x slab: 131 rows x 512B
#pragma unroll
    for (int it = 0; it < 17; it++) {
        int idx = it * 256 + tid;
        if (idx < 131 * 32) {
            int ss = idx >> 5, c16 = idx & 31;
            int grow = by * 128 + ss - 3;
            bool v = (grow >= 0);
            const bf16* src = xsrc + ((size_t)bz * LL + (v ? grow : 0)) * DD + c16 * 8;
            cp16(smem + swzx((uint32_t)ss, (uint32_t)c16 * 16), src, v);
        }
    }
    load_convB(smem, 0, 0, tid, bx, layer);
    CP_COMMIT();                         // group: slab + B0

    float acc[16][4] = {};
    uint32_t xbase = s2u(smem);

#pragma unroll 1
    for (int i = 0; i < 16; i++) {
        asm volatile("cp.async.wait_group 0;" ::: "memory");
        __syncthreads();
        if (i + 1 < 16) { load_convB(smem, (i + 1) & 1, (i + 1) * 64, tid, bx, layer); CP_COMMIT(); }
        int tap = i >> 2, d0 = (i & 3) * 64;
        uint32_t bbase = s2u(smem + CONV_B_OFF + (i & 1) * 16384);
#pragma unroll
        for (int kk = 0; kk < 4; kk++) {
            int ks = ((kk + wm) & 3) * 16;
            uint32_t a[2][4];
#pragma unroll
            for (int t = 0; t < 2; t++) {
                uint32_t row = wm * 32 + t * 16 + ((lane >> 3) & 1) * 8 + (lane & 7);
                uint32_t ss = row + tap;
                uint32_t cb = (d0 + ks + (lane >> 4) * 8) * 2;
                uint32_t ad = xbase + swzx(ss, cb);
                asm volatile("ldmatrix.sync.aligned.m8n8.x4.shared.b16 {%0,%1,%2,%3},[%4];"
                             : "=r"(a[t][0]), "=r"(a[t][1]), "=r"(a[t][2]), "=r"(a[t][3])
                             : "r"(ad));
            }
            uint32_t b[8][2];
#pragma unroll
            for (int p4 = 0; p4 < 4; p4++) {
                uint32_t r0, r1, r2, r3;
                uint32_t row = wn * 64 + p4 * 16 + (lane >> 4) * 8 + (lane & 7);
                uint32_t cb = (ks + ((lane >> 3) & 1) * 8) * 2;
                uint32_t ad = bbase + swz128(row * 128 + cb);
                asm volatile("ldmatrix.sync.aligned.m8n8.x4.shared.b16 {%0,%1,%2,%3},[%4];"
                             : "=r"(r0), "=r"(r1), "=r"(r2), "=r"(r3) : "r"(ad));
                b[2 * p4][0] = r0; b[2 * p4][1] = r1;
                b[2 * p4 + 1][0] = r2; b[2 * p4 + 1][1] = r3;
            }
#pragma unroll
            for (int t = 0; t < 2; t++)
#pragma unroll
                for (int j = 0; j < 8; j++)
                    mma_bf16(acc[t * 8 + j], a[t], b[j]);
        }
    }

    // GLU + residual epilogue (residual from resident slab: row r -> ss=r+3)
#pragma unroll
    for (int t = 0; t < 2; t++) {
        int r = wm * 32 + t * 16 + (lane >> 2);
        size_t gr0 = (size_t)bz * LL + by * 128 + r;
        size_t gr1 = gr0 + 8;
#pragma unroll
        for (int j = 0; j < 4; j++) {
            int pc = wn * 64 + j * 8 + (lane & 3) * 2;
            int pnA = bx * 128 + pc, pnG = pnA + 32;
            float ba0 = biasP[pnA], ba1 = biasP[pnA + 1];
            float bg0 = biasP[pnG], bg1 = biasP[pnG + 1];
            float* a = acc[t * 8 + j];
            float* g = acc[t * 8 + j + 4];
            int ocol = (bx * 2 + wn) * 32 + j * 8 + (lane & 3) * 2;
            float v0 = (a[0] + ba0) * sigmoidf_(g[0] + bg0);
            float v1 = (a[1] + ba1) * sigmoidf_(g[1] + bg1);
            float v2 = (a[2] + ba0) * sigmoidf_(g[2] + bg0);
            float v3 = (a[3] + ba1) * sigmoidf_(g[3] + bg1);
            uint32_t ss0 = (uint32_t)r + 3, ss1 = ss0 + 8;
            bf162 r0 = *(bf162*)(smem + swzx(ss0, (uint32_t)ocol * 2));
            bf162 r1 = *(bf162*)(smem + swzx(ss1, (uint32_t)ocol * 2));
            v0 += __bfloat162float(r0.x); v1 += __bfloat162float(r0.y);
            v2 += __bfloat162float(r1.x); v3 += __bfloat162float(r1.y);
            *(bf162*)(xdst + gr0 * DD + ocol) = __floats2bfloat162_rn(v0, v1);
            *(bf162*)(xdst + gr1 * DD + ocol) = __floats2bfloat162_rn(v2, v3);
        }
    }
}

// ---------------- prep A: zero sums + embed ----------------
#define PA0 256
#define PA1 (PA0 + 65536)
__global__ __launch_bounds__(256) void k_prep_embed(const int* __restrict__ q,
                                                    const int* __restrict__ c,
                                                    const float* __restrict__ Eq,
                                                    const float* __restrict__ Ec) {
    int bid = blockIdx.x, tid = threadIdx.x;
    if (bid < PA0) {
        int id = bid * 256 + tid;
        g_rowsum[id] = 0.f;
        g_s1[id] = 0.f;
    } else {
        int r = bid - PA0, d = tid;
        int qi = q[r], ci = c[r];
        g_LIS[(size_t)r * TWO_D + d]      = __float2bfloat16(Eq[(size_t)qi * DD + d]);
        g_LIS[(size_t)r * TWO_D + DD + d] = __float2bfloat16(Ec[(size_t)ci * DD + d]);
    }
}

// ---------------- prep B: weights/u/cqc (side stream) ----------------
#define PB0 2560
#define PB2 (PB0 + 2)
#define PBU (PB2 + 8)
#define PB3 (PBU + 768)
#define PB4 (PB3 + 16384)
__global__ __launch_bounds__(256) void k_prep_rest(const float* __restrict__ W1w,
                                                   const float* __restrict__ W2w,
                                                   const float* __restrict__ b1,
                                                   const float* __restrict__ b2,
                                                   const float* __restrict__ convb,
                                                   const float* __restrict__ convw,
                                                   const float* __restrict__ cqc,
                                                   const float* __restrict__ Ec) {
    __shared__ bf16 tile[64][40];
    int bid = blockIdx.x, tid = threadIdx.x;
    if (bid < PB0) {
        int id = bid * 256 + tid;
        if (id < TWO_D * HD) {
            int pn = id / HD, k = id % HD;
            int n = unpackN64(pn);
            float v = (n < DD) ? W1w[(size_t)n * HD + k] : W2w[(size_t)(n - DD) * HD + k];
            g_WmlpP[id] = __float2bfloat16(v);
        }
    } else if (bid < PB2) {
        int pn = (bid - PB0) * 256 + tid;
        int n = unpackN64(pn);
        g_bP[pn] = (n < DD) ? b1[n] : b2[n - DD];
        for (int l = 0; l < 3; l++)
            g_bconvP[l * TWO_D + pn] = convb[l * TWO_D + n];
    } else if (bid < PBU) {
        int t = (bid - PB2) * 256 + tid;
        int table = t >> 10;
        int rem = t & 1023;
        int e = rem >> 9, pn = rem & 511;
        int n = unpackN64(pn);
        const float* wr = (n < DD) ? (W1w + (size_t)n * HD) : (W2w + (size_t)(n - DD) * HD);
        int ko = table ? 768 : 256;
        const float* ec = Ec + e * DD;
        float s = 0.f;
        for (int k = 0; k < DD; k++) s += ec[k] * wr[ko + k];
        if (table == 0) g_u1[e * TWO_D + pn] = s;
        else            g_u2[e * TWO_D + pn] = s;
    } else if (bid < PB3) {
        int id = bid - PBU;
        int kx = id & 15, ny = (id >> 4) & 15, l = id >> 8;
        int k0 = kx * 64, n0 = ny * 32;
        {
            int row = tid >> 2, seg = tid & 3;
            const float* src = convw + ((size_t)(l * 1024 + k0 + row)) * TWO_D + n0 + seg * 8;
            float4 v0 = *(const float4*)src;
            float4 v1 = *(const float4*)(src + 4);
            tile[row][seg * 8 + 0] = __float2bfloat16(v0.x);
            tile[row][seg * 8 + 1] = __float2bfloat16(v0.y);
            tile[row][seg * 8 + 2] = __float2bfloat16(v0.z);
            tile[row][seg * 8 + 3] = __float2bfloat16(v0.w);
            tile[row][seg * 8 + 4] = __float2bfloat16(v1.x);
            tile[row][seg * 8 + 5] = __float2bfloat16(v1.y);
            tile[row][seg * 8 + 6] = __float2bfloat16(v1.z);
            tile[row][seg * 8 + 7] = __float2bfloat16(v1.w);
        }
        __syncthreads();
        {
            int s = (n0 < 256) ? (n0 >> 5) : ((n0 - 256) >> 5);
            int pn0 = s * 64 + ((n0 < 256) ? 0 : 32);
            int row = tid >> 3, seg = tid & 7;
            bf16 buf[8];
#pragma unroll
            for (int j = 0; j < 8; j++) buf[j] = tile[seg * 8 + j][row];
            bf16* dst = g_convwP + ((size_t)(l * TWO_D + pn0 + row)) * 1024 + k0 + seg * 8;
            *(uint4*)dst = *(uint4*)buf;
        }
    } else {
        size_t id = (size_t)(bid - PB3) * 256 + tid;
        float4 v = ((const float4*)cqc)[id];
        bf162* o = (bf162*)g_cqc;
        o[id * 2] = __floats2bfloat162_rn(v.x, v.y);
        o[id * 2 + 1] = __floats2bfloat162_rn(v.z, v.w);
    }
}

// ---------------- predict ----------------
__global__ __launch_bounds__(256) void k_predict(const bf16* __restrict__ xf,
                                                 float* __restrict__ out) {
    int warp = threadIdx.x >> 5, lane = threadIdx.x & 31;
    int o = blockIdx.x * 8 + warp;
    if (o >= BB * (LL - 1)) return;
    int b = o / (LL - 1), l = o % (LL - 1);
    const bf16* xr = xf + (size_t)(b * LL + l) * DD;
    const bf16* qr = g_LIS + (size_t)(b * LL + l + 1) * TWO_D;
    float s = 0.f;
    for (int d = lane; d < DD; d += 32)
        s += __bfloat162float(xr[d]) * __bfloat162float(qr[d]);
#pragma unroll
    for (int off = 16; off > 0; off >>= 1) s += __shfl_down_sync(0xffffffffu, s, off);
    if (lane == 0) out[o] = sigmoidf_(s);
}

static bf16* addr_x() { void* p; cudaGetSymbolAddress(&p, g_x); return (bf16*)p; }
static bf16* addr_x2() { void* p; cudaGetSymbolAddress(&p, g_x2); return (bf16*)p; }
static float* addr_bP() { void* p; cudaGetSymbolAddress(&p, g_bP); return (float*)p; }
static float* addr_bconvP() { void* p; cudaGetSymbolAddress(&p, g_bconvP); return (float*)p; }

// ---------------- launch ----------------
extern "C" void kernel_launch(void* const* d_in, const int* in_sizes, int n_in,
                              void* d_out, int out_size) {
    (void)in_sizes; (void)n_in; (void)out_size;
    const int*   q     = (const int*)d_in[0];
    const int*   c     = (const int*)d_in[1];
    const float* cqc   = (const float*)d_in[2];
    const float* Eq    = (const float*)d_in[3];
    const float* Ec    = (const float*)d_in[4];
    const float* W1w   = (const float*)d_in[5];
    const float* W1b   = (const float*)d_in[6];
    const float* W2w   = (const float*)d_in[7];
    const float* W2b   = (const float*)d_in[8];
    const float* convw = (const float*)d_in[9];
    const float* convb = (const float*)d_in[10];
    float* out = (float*)d_out;

    static bf16 *xA = nullptr, *xB = nullptr;
    static float *bP = nullptr, *bconvP = nullptr;
    static cudaStream_t s2;
    static cudaEvent_t evF, evJ;
    static bool init_done = false;
    if (!init_done) {
        cudaFuncSetAttribute(k_gemm<0>, cudaFuncAttributeMaxDynamicSharedMemorySize, SMEM_TOTAL);
        cudaFuncSetAttribute(k_gemm<1>, cudaFuncAttributeMaxDynamicSharedMemorySize, SMEM_TOTAL);
        cudaFuncSetAttribute(k_gemm<2>, cudaFuncAttributeMaxDynamicSharedMemorySize, SMEM_TOTAL);
        cudaFuncSetAttribute(k_conv, cudaFuncAttributeMaxDynamicSharedMemorySize, CONV_SMEM);
        xA = addr_x(); xB = addr_x2();
        bP = addr_bP(); bconvP = addr_bconvP();
        cudaStreamCreateWithFlags(&s2, cudaStreamNonBlocking);
        cudaEventCreateWithFlags(&evF, cudaEventDisableTiming);
        cudaEventCreateWithFlags(&evJ, cudaEventDisableTiming);
        init_done = true;
    }

    cudaEventRecord(evF, 0);
    cudaStreamWaitEvent(s2, evF, 0);
    k_prep_rest<<<PB4, 256, 0, s2>>>(W1w, W2w, W1b, W2b, convb, convw, cqc, Ec);
    cudaEventRecord(evJ, s2);

    k_prep_embed<<<PA1, 256>>>(q, c, Eq, Ec);
    k_gemm<0><<<dim3(8, 8, BB), 256, SMEM_TOTAL>>>(nullptr, nullptr, c);
    k_gemm<1><<<dim3(2, 8, BB), 256, SMEM_TOTAL>>>(nullptr, nullptr, nullptr);

    cudaStreamWaitEvent(0, evJ, 0);
    k_gemm<2><<<dim3(4, 512, 1), 256, SMEM_TOTAL>>>(xA, bP, c);
    bf16* src = xA;
    bf16* dst = xB;
    for (int l = 0; l < 3; l++) {
        k_conv<<<dim3(4, 8, BB), 256, CONV_SMEM>>>(src, dst, bconvP + l * TWO_D, l);
        bf16* t = src; src = dst; dst = t;
    }
    k_predict<<<(BB * (LL - 1) + 7) / 8, 256>>>(src, out);
}